// round 12
// baseline (speedup 1.0000x reference)
#include <cuda_runtime.h>
#include <cstdint>

// Model_35347580846430: reflect-pad depthwise moving average, W=25, PAD=12
// x: [B=64, T=4096, N=128] f32, out same shape.
// out[b,t,n] = mean_{k=-12..12} x[b, reflect(t+k), n]
//
// R12: more phase diversity. Scaling law so far: 2 blocks/SM -> 64% DRAM,
// 5 blocks/SM -> 70%. R11 missed its 6th block by 1KB of smem. Since T_TILE
// must divide 4096 (power of two), shrink to T_TILE=64 with N-half blocks:
// ROWS=88, 22.5KB buffer -> 8 resident blocks/SM (launch_bounds(128,8),
// reg-file bound), 32 warps, 8 independent load/compute cycles per SM.
// Halo read-amp (1.375) is L2-only: measured DRAM traffic has sat below the
// compulsory floor since R7 (halos dedup in L2).

#define B_DIM  64
#define T_DIM  4096
#define N_DIM  128
#define PAD    12
#define WIN    25
#define T_TILE 64
#define HALO   (2 * PAD)            // 24
#define ROWS   (T_TILE + HALO)      // 88 smem rows
#define N4     (N_DIM / 4)          // 32 float4 per full row
#define N4H    16                   // float4 per half row (this block's share)
#define NTHR   128
#define KROWS  8                    // output rows per thread
#define SMEM_BYTES (ROWS * N4H * 16)    // 22528

__device__ __forceinline__ int reflect_idx(int t) {
    // np.pad 'reflect': x[-1] -> x[1], x[T] -> x[T-2]
    t = (t < 0) ? -t : t;
    t = (t >= T_DIM) ? (2 * (T_DIM - 1) - t) : t;
    return t;
}

__global__ __launch_bounds__(NTHR, 8)
void ma25_kernel(const float4* __restrict__ x, float4* __restrict__ out) {
    extern __shared__ float4 smem[];          // [ROWS][N4H]

    const int tid  = threadIdx.x;
    const int lane = tid & 15;                // float4 column 0..15 within half
    const int grp  = tid >> 4;                // 0..7 row groups
    const int b    = blockIdx.y;
    const int t0   = blockIdx.x * T_TILE;
    const int n0   = blockIdx.z * N4H;        // which N-half

    const float4* __restrict__ xb = x + (size_t)b * T_DIM * N4 + n0 + lane;

    // ---- Load phase: 88 rows, 8 rows/iter, 11 cp.asyncs per thread.
    #pragma unroll
    for (int it = 0; it < ROWS / 8; it++) {
        const int r = it * 8 + grp;
        const int t = reflect_idx(t0 - PAD + r);
        const float4* src = xb + (size_t)t * N4;
        uint32_t dst = (uint32_t)__cvta_generic_to_shared(&smem[r * N4H + lane]);
        asm volatile("cp.async.cg.shared.global [%0], [%1], 16;"
                     :: "r"(dst), "l"(src) : "memory");
    }
    asm volatile("cp.async.commit_group;" ::: "memory");
    asm volatile("cp.async.wait_group 0;" ::: "memory");
    __syncthreads();

    // ---- Compute phase: thread owns column `lane`, output rows [r0, r0+8).
    const int r0 = grp * KROWS;
    const float inv = 1.0f / (float)WIN;

    float4* __restrict__ ob = out + (size_t)(b * T_DIM + t0) * N4 + n0 + lane;

    float sx = 0.f, sy = 0.f, sz = 0.f, sw = 0.f;
    #pragma unroll
    for (int j = 0; j < HALO; j++) {
        float4 v = smem[(r0 + j) * N4H + lane];
        sx += v.x; sy += v.y; sz += v.z; sw += v.w;
    }

    #pragma unroll
    for (int k = 0; k < KROWS; k++) {
        const int r = r0 + k;
        float4 vin = smem[(r + HALO) * N4H + lane];   // incoming row r+24
        float wx = sx + vin.x, wy = sy + vin.y, wz = sz + vin.z, ww = sw + vin.w;

        float4 o; o.x = wx * inv; o.y = wy * inv; o.z = wz * inv; o.w = ww * inv;
        ob[(size_t)r * N4] = o;

        float4 vout = smem[r * N4H + lane];           // outgoing row r
        sx = wx - vout.x; sy = wy - vout.y;
        sz = wz - vout.z; sw = ww - vout.w;
    }
}

extern "C" void kernel_launch(void* const* d_in, const int* in_sizes, int n_in,
                              void* d_out, int out_size) {
    const float4* x = (const float4*)d_in[0];
    float4* out = (float4*)d_out;

    cudaFuncSetAttribute(ma25_kernel,
                         cudaFuncAttributeMaxDynamicSharedMemorySize, SMEM_BYTES);

    dim3 block(NTHR);
    dim3 grid(T_DIM / T_TILE, B_DIM, 2);           // (64, 64, 2) = 8192 blocks
    ma25_kernel<<<grid, block, SMEM_BYTES>>>(x, out);
}